// round 1
// baseline (speedup 1.0000x reference)
#include <cuda_runtime.h>

// ---------------------------------------------------------------------------
// SparseResNet on GB300 — Round 1: fp32 implicit-gather SGEMM baseline.
//
// Pipeline (matches reference):
//   f = relu(bn(conv(x,  nb1, w_s1)))                       [27648,128]
//   f = block(f, nbs, w11,g11,b11, w12,g12,b12)             [27648,128]
//   f = block(f, nbs, w21,g21,b21, w22,g22,b22)             [27648,128]
//   out = relu(bn(conv(f, nb2, w_s2)))                      [46080, 32]
// block(f) = relu(bn(conv(relu(bn(conv(f,w1))),w2)) + f)
// ---------------------------------------------------------------------------

#define M1 27648
#define M2 46080
#define NBLK 144          // bn_stats grid (fixed => deterministic reduction)

// scratch (allocation-free rule: __device__ globals)
__device__ float g_A[M1 * 128];
__device__ float g_B[M1 * 128];
__device__ float g_C[M1 * 128];
__device__ float g_D[M2 * 32];
__device__ float g_psum[NBLK * 128];
__device__ float g_pssq[NBLK * 128];
__device__ float g_scale[128];
__device__ float g_shift[128];

// ---------------------------------------------------------------------------
// Implicit-gather tiled SGEMM:
//   out[m, co] = sum_k sum_ci ( nb[k,m] >= 0 ? x[nb[k,m], ci] : 0 ) * w[k,ci,co]
// Block computes a BM x BN output tile. Rulebook indices for the current
// offset k staged in smem; A tile stored transposed [BK][BM+4].
// Shapes are exact multiples of tiles (27648/128, 46080/128, Cin%16==0),
// so no boundary predicates.
// ---------------------------------------------------------------------------
template <int BM, int BN, int BK, int TM, int TN, int CIN, int COUT>
__global__ void __launch_bounds__((BM / TM) * (BN / TN))
spconv_kernel(const float* __restrict__ x, const float* __restrict__ w,
              const int* __restrict__ nb, float* __restrict__ out, int M) {
    constexpr int NT  = (BM / TM) * (BN / TN);
    constexpr int BNX = BN / TN;

    __shared__ __align__(16) float As[BK][BM + 4];
    __shared__ __align__(16) float Bs[BK][BN];
    __shared__ int idxs[BM];

    const int m0  = blockIdx.x * BM;
    const int tid = threadIdx.x;
    const int tx  = tid % BNX;
    const int ty  = tid / BNX;

    float acc[TM][TN];
#pragma unroll
    for (int i = 0; i < TM; ++i)
#pragma unroll
        for (int j = 0; j < TN; ++j) acc[i][j] = 0.f;

    for (int k = 0; k < 27; ++k) {
        __syncthreads();  // previous-iter readers done before idxs overwrite
        for (int i = tid; i < BM; i += NT) idxs[i] = nb[k * M + m0 + i];
        __syncthreads();

        for (int c0 = 0; c0 < CIN; c0 += BK) {
            // --- gather A tile (transposed into smem) ---
            constexpr int LD4 = BM * BK / 4;
#pragma unroll
            for (int t = tid; t < LD4; t += NT) {
                int row = t / (BK / 4);
                int q   = t % (BK / 4);
                int r   = idxs[row];
                float4 v = make_float4(0.f, 0.f, 0.f, 0.f);
                if (r >= 0)
                    v = *reinterpret_cast<const float4*>(
                        x + (size_t)r * CIN + c0 + q * 4);
                As[q * 4 + 0][row] = v.x;
                As[q * 4 + 1][row] = v.y;
                As[q * 4 + 2][row] = v.z;
                As[q * 4 + 3][row] = v.w;
            }
            // --- load B (weight) tile ---
            constexpr int LB4 = BK * BN / 4;
            const float* wp = w + ((size_t)k * CIN + c0) * COUT;
#pragma unroll
            for (int t = tid; t < LB4; t += NT) {
                int row = t / (BN / 4);
                int q   = t % (BN / 4);
                *reinterpret_cast<float4*>(&Bs[row][q * 4]) =
                    *reinterpret_cast<const float4*>(wp + row * COUT + q * 4);
            }
            __syncthreads();

#pragma unroll
            for (int c = 0; c < BK; ++c) {
                float a[TM], b[TN];
#pragma unroll
                for (int i = 0; i < TM; i += 4) {
                    float4 v = *reinterpret_cast<const float4*>(&As[c][ty * TM + i]);
                    a[i] = v.x; a[i + 1] = v.y; a[i + 2] = v.z; a[i + 3] = v.w;
                }
#pragma unroll
                for (int j = 0; j < TN; j += 4) {
                    float4 v = *reinterpret_cast<const float4*>(&Bs[c][tx * TN + j]);
                    b[j] = v.x; b[j + 1] = v.y; b[j + 2] = v.z; b[j + 3] = v.w;
                }
#pragma unroll
                for (int i = 0; i < TM; ++i)
#pragma unroll
                    for (int j = 0; j < TN; ++j)
                        acc[i][j] = fmaf(a[i], b[j], acc[i][j]);
            }
            __syncthreads();
        }
    }

    float* o = out + (size_t)m0 * COUT;
#pragma unroll
    for (int i = 0; i < TM; ++i) {
        int row = ty * TM + i;
#pragma unroll
        for (int j = 0; j < TN; j += 4) {
            float4 v = make_float4(acc[i][j], acc[i][j + 1],
                                   acc[i][j + 2], acc[i][j + 3]);
            *reinterpret_cast<float4*>(o + (size_t)row * COUT + tx * TN + j) = v;
        }
    }
}

// ---------------------------------------------------------------------------
// BatchNorm (training mode, biased variance) — deterministic 2-stage reduce.
// Stage 1: each of NBLK blocks accumulates per-channel sum / sumsq over a
// fixed, block-indexed row set (coalesced: thread owns one channel).
// ---------------------------------------------------------------------------
template <int C>
__global__ void bn_stats(const float* __restrict__ f, int M) {
    constexpr int TPC = 256 / C;  // row-parallel threads per channel
    const int tx = threadIdx.x % C;
    const int ty = threadIdx.x / C;
    float s = 0.f, ss = 0.f;
    for (int r = blockIdx.x * TPC + ty; r < M; r += gridDim.x * TPC) {
        float v = f[(size_t)r * C + tx];
        s += v;
        ss += v * v;
    }
    __shared__ float s1[256], s2[256];
    s1[threadIdx.x] = s;
    s2[threadIdx.x] = ss;
    __syncthreads();
    if (ty == 0) {
#pragma unroll
        for (int t = 1; t < TPC; ++t) {
            s  += s1[tx + t * C];
            ss += s2[tx + t * C];
        }
        g_psum[blockIdx.x * C + tx] = s;
        g_pssq[blockIdx.x * C + tx] = ss;
    }
}

// Stage 2: fixed-order final reduce -> scale/shift.
template <int C>
__global__ void bn_finalize(const float* __restrict__ g,
                            const float* __restrict__ b, int M) {
    int c = threadIdx.x;
    float s = 0.f, ss = 0.f;
    for (int i = 0; i < NBLK; ++i) {
        s  += g_psum[i * C + c];
        ss += g_pssq[i * C + c];
    }
    float inv_m = 1.f / (float)M;
    float mu  = s * inv_m;
    float var = ss * inv_m - mu * mu;
    float sc  = g[c] * rsqrtf(var + 1e-5f);
    g_scale[c] = sc;
    g_shift[c] = b[c] - mu * sc;
}

// Fused normalize (+ optional residual) (+ optional ReLU).
template <int C, bool RELU, bool RES>
__global__ void bn_apply(const float* __restrict__ f, const float* __restrict__ res,
                         float* __restrict__ out, int M) {
    __shared__ float sc[C], sh[C];
    for (int c = threadIdx.x; c < C; c += blockDim.x) {
        sc[c] = g_scale[c];
        sh[c] = g_shift[c];
    }
    __syncthreads();
    int total4 = M * C / 4;
    for (int i = blockIdx.x * blockDim.x + threadIdx.x; i < total4;
         i += gridDim.x * blockDim.x) {
        float4 v = reinterpret_cast<const float4*>(f)[i];
        int c0 = (i * 4) % C;
        v.x = v.x * sc[c0 + 0] + sh[c0 + 0];
        v.y = v.y * sc[c0 + 1] + sh[c0 + 1];
        v.z = v.z * sc[c0 + 2] + sh[c0 + 2];
        v.w = v.w * sc[c0 + 3] + sh[c0 + 3];
        if (RES) {
            float4 r = reinterpret_cast<const float4*>(res)[i];
            v.x += r.x; v.y += r.y; v.z += r.z; v.w += r.w;
        }
        if (RELU) {
            v.x = fmaxf(v.x, 0.f); v.y = fmaxf(v.y, 0.f);
            v.z = fmaxf(v.z, 0.f); v.w = fmaxf(v.w, 0.f);
        }
        reinterpret_cast<float4*>(out)[i] = v;
    }
}

// ---------------------------------------------------------------------------
extern "C" void kernel_launch(void* const* d_in, const int* in_sizes, int n_in,
                              void* d_out, int out_size) {
    (void)in_sizes; (void)n_in; (void)out_size;

    const float* x    = (const float*)d_in[0];
    const float* w_s1 = (const float*)d_in[1];
    const float* g_s1 = (const float*)d_in[2];
    const float* b_s1 = (const float*)d_in[3];
    const float* w11  = (const float*)d_in[4];
    const float* g11  = (const float*)d_in[5];
    const float* b11  = (const float*)d_in[6];
    const float* w12  = (const float*)d_in[7];
    const float* g12  = (const float*)d_in[8];
    const float* b12  = (const float*)d_in[9];
    const float* w21  = (const float*)d_in[10];
    const float* g21  = (const float*)d_in[11];
    const float* b21  = (const float*)d_in[12];
    const float* w22  = (const float*)d_in[13];
    const float* g22  = (const float*)d_in[14];
    const float* b22  = (const float*)d_in[15];
    const float* w_s2 = (const float*)d_in[16];
    const float* g_s2 = (const float*)d_in[17];
    const float* b_s2 = (const float*)d_in[18];
    const int*   nb1  = (const int*)d_in[19];
    const int*   nbs  = (const int*)d_in[20];
    const int*   nb2  = (const int*)d_in[21];
    float* out = (float*)d_out;

    float *A, *B, *C, *D;
    cudaGetSymbolAddress((void**)&A, g_A);
    cudaGetSymbolAddress((void**)&B, g_B);
    cudaGetSymbolAddress((void**)&C, g_C);
    cudaGetSymbolAddress((void**)&D, g_D);

    const int GRID1 = M1 / 128;  // 216
    const int GRID2 = M2 / 128;  // 360
    const int EW_GRID = 512, EW_THR = 256;

    // spconv1: x[9216,256] -> A[27648,128], bn+relu in place
    spconv_kernel<128, 128, 16, 8, 8, 256, 128><<<GRID1, 256>>>(x, w_s1, nb1, A, M1);
    bn_stats<128><<<NBLK, 256>>>(A, M1);
    bn_finalize<128><<<1, 128>>>(g_s1, b_s1, M1);
    bn_apply<128, true, false><<<EW_GRID, EW_THR>>>(A, nullptr, A, M1);

    // block1
    spconv_kernel<128, 128, 16, 8, 8, 128, 128><<<GRID1, 256>>>(A, w11, nbs, B, M1);
    bn_stats<128><<<NBLK, 256>>>(B, M1);
    bn_finalize<128><<<1, 128>>>(g11, b11, M1);
    bn_apply<128, true, false><<<EW_GRID, EW_THR>>>(B, nullptr, B, M1);

    spconv_kernel<128, 128, 16, 8, 8, 128, 128><<<GRID1, 256>>>(B, w12, nbs, C, M1);
    bn_stats<128><<<NBLK, 256>>>(C, M1);
    bn_finalize<128><<<1, 128>>>(g12, b12, M1);
    bn_apply<128, true, true><<<EW_GRID, EW_THR>>>(C, A, A, M1);  // relu(bn(C)+A) -> A

    // block2
    spconv_kernel<128, 128, 16, 8, 8, 128, 128><<<GRID1, 256>>>(A, w21, nbs, B, M1);
    bn_stats<128><<<NBLK, 256>>>(B, M1);
    bn_finalize<128><<<1, 128>>>(g21, b21, M1);
    bn_apply<128, true, false><<<EW_GRID, EW_THR>>>(B, nullptr, B, M1);

    spconv_kernel<128, 128, 16, 8, 8, 128, 128><<<GRID1, 256>>>(B, w22, nbs, C, M1);
    bn_stats<128><<<NBLK, 256>>>(C, M1);
    bn_finalize<128><<<1, 128>>>(g22, b22, M1);
    bn_apply<128, true, true><<<EW_GRID, EW_THR>>>(C, A, A, M1);

    // spconv2: A[27648,128] -> D[46080,32] -> out
    spconv_kernel<128, 32, 16, 4, 4, 128, 32><<<GRID2, 256>>>(A, w_s2, nb2, D, M2);
    bn_stats<32><<<NBLK, 256>>>(D, M2);
    bn_finalize<32><<<1, 32>>>(g_s2, b_s2, M2);
    bn_apply<32, true, false><<<EW_GRID, EW_THR>>>(D, nullptr, out, M2);
}